// round 3
// baseline (speedup 1.0000x reference)
#include <cuda_runtime.h>
#include <math.h>

#define BATCH 2
#define CH    256
#define HH    96
#define WW    96
#define HW    (HH*WW)        // 9216
#define OUTC  256
#define KTAPS 9
#define KDIM  (KTAPS*CH)     // 2304
#define MROWS (BATCH*HW)     // 18432
#define NOFF  32             // 27 padded to 32

struct __align__(16) SInfo { int i0,i1,i2,i3; float w0,w1,w2,w3; };

// ---- scratch (device globals: allocation-free) ----
__device__ float g_xT [MROWS*CH];        // x in NHWC     [b*HW+p][c]
__device__ float g_h1T[MROWS*CH];        // layer-1 out NHWC
__device__ float g_h2T[MROWS*CH];        // layer-2 out NHWC
__device__ float g_om [MROWS*NOFF];      // offset-conv out per pixel (27 used)
__device__ SInfo g_sinfo[MROWS*KTAPS];   // per (pixel,tap) bilinear indices+weights
__device__ float g_bwoff [2][KDIM*NOFF]; // offset weights, K-major [k][j]
__device__ float g_bwmain[2][KDIM*OUTC]; // main weights,   K-major [k][o]

// ---------------- weight prep (transpose to K-major) ----------------
__global__ void prep_woff_k(const float* __restrict__ woff, int layer) {
    int idx = blockIdx.x*256 + threadIdx.x;
    if (idx >= KDIM*NOFF) return;
    int j   = idx & 31;
    int kc  = idx >> 5;
    int tap = kc / CH, c = kc % CH;
    g_bwoff[layer][idx] = (j < 27) ? woff[(j*CH + c)*KTAPS + tap] : 0.0f;
}

__global__ void prep_wmain_k(const float* __restrict__ w, int layer) {
    int idx = blockIdx.x*256 + threadIdx.x;
    if (idx >= KDIM*OUTC) return;
    int o   = idx & 255;
    int kc  = idx >> 8;
    int tap = kc / CH, c = kc % CH;
    g_bwmain[layer][idx] = w[(o*CH + c)*KTAPS + tap];
}

// ---------------- layout transposes ----------------
__global__ void nchw_to_nhwc_k(const float* __restrict__ src) {
    __shared__ float t[32][33];
    int b  = blockIdx.z;
    int p0 = blockIdx.x*32, c0 = blockIdx.y*32;
    int tx = threadIdx.x,  ty = threadIdx.y;
    #pragma unroll
    for (int i = 0; i < 32; i += 8)
        t[ty+i][tx] = src[(size_t)(b*CH + c0+ty+i)*HW + p0 + tx];
    __syncthreads();
    #pragma unroll
    for (int i = 0; i < 32; i += 8)
        g_xT[(size_t)(b*HW + p0+ty+i)*CH + c0 + tx] = t[tx][ty+i];
}

__global__ void nhwc_to_nchw_k(float* __restrict__ dst) {
    __shared__ float t[32][33];
    int b  = blockIdx.z;
    int p0 = blockIdx.x*32, c0 = blockIdx.y*32;
    int tx = threadIdx.x,  ty = threadIdx.y;
    #pragma unroll
    for (int i = 0; i < 32; i += 8)
        t[ty+i][tx] = g_h2T[(size_t)(b*HW + p0+ty+i)*CH + c0 + tx];
    __syncthreads();
    #pragma unroll
    for (int i = 0; i < 32; i += 8)
        dst[(size_t)(b*CH + c0+ty+i)*HW + p0 + tx] = t[tx][ty+i];
}

// ---------------- offset conv: implicit-im2col GEMM ----------------
// M=18432, N=32 (27 used), K=2304.  BM=128, BN=32, BK=32; 256 thr; 4x4 micro.
__launch_bounds__(256, 2)
__global__ void gemm_off_k(int layer, const float* __restrict__ bias) {
    __shared__ float As[32][128];
    __shared__ float Bs[32][32];
    const float* in = (layer == 0) ? g_xT : g_h1T;
    const float* Bw = g_bwoff[layer];
    int tid = threadIdx.x;
    int bm  = blockIdx.x;
    int ty  = tid >> 3, tx = tid & 7;        // compute mapping
    int px  = tid & 127, cg = tid >> 7;      // staging mapping
    int cc  = cg * 16;
    int gp  = bm*128 + px;
    int b   = gp / HW, p = gp % HW;
    int y   = p / WW, x = p % WW;
    const float* inb = in + (size_t)b*HW*CH;

    float acc[4][4] = {};

    for (int kt = 0; kt < 72; kt++) {
        int tap = kt >> 3;
        int c0  = (kt & 7) * 32;
        // --- gmem loads (before sync) ---
        float4 bfrag = ((const float4*)(Bw + (size_t)(tap*CH + c0)*NOFF))[tid];
        int ny = y + tap/3 - 1;
        int nx = x + tap%3 - 1;
        float4 d0 = {0,0,0,0}, d1 = d0, d2 = d0, d3 = d0;
        if ((unsigned)ny < HH && (unsigned)nx < WW) {
            const float* s = inb + (size_t)(ny*WW + nx)*CH + c0 + cc;
            d0 = *(const float4*)(s);
            d1 = *(const float4*)(s + 4);
            d2 = *(const float4*)(s + 8);
            d3 = *(const float4*)(s + 12);
        }
        __syncthreads();
        As[cc+ 0][px]=d0.x; As[cc+ 1][px]=d0.y; As[cc+ 2][px]=d0.z; As[cc+ 3][px]=d0.w;
        As[cc+ 4][px]=d1.x; As[cc+ 5][px]=d1.y; As[cc+ 6][px]=d1.z; As[cc+ 7][px]=d1.w;
        As[cc+ 8][px]=d2.x; As[cc+ 9][px]=d2.y; As[cc+10][px]=d2.z; As[cc+11][px]=d2.w;
        As[cc+12][px]=d3.x; As[cc+13][px]=d3.y; As[cc+14][px]=d3.z; As[cc+15][px]=d3.w;
        ((float4*)Bs)[tid] = bfrag;
        __syncthreads();

        #pragma unroll
        for (int kk = 0; kk < 32; kk++) {
            float a[4], bb[4];
            *(float4*)a  = *(const float4*)&As[kk][ty*4];
            *(float4*)bb = *(const float4*)&Bs[kk][tx*4];
            #pragma unroll
            for (int i = 0; i < 4; i++)
                #pragma unroll
                for (int j = 0; j < 4; j++)
                    acc[i][j] += a[i]*bb[j];
        }
    }

    int j0 = tx*4;
    float bv[4];
    #pragma unroll
    for (int j = 0; j < 4; j++) bv[j] = (j0 + j < 27) ? bias[j0 + j] : 0.0f;
    #pragma unroll
    for (int i = 0; i < 4; i++) {
        int row = bm*128 + ty*4 + i;
        float4 o4 = make_float4(acc[i][0]+bv[0], acc[i][1]+bv[1],
                                acc[i][2]+bv[2], acc[i][3]+bv[3]);
        *(float4*)&g_om[(size_t)row*NOFF + j0] = o4;
    }
}

// ---------------- sample coordinates + bilinear weights ----------------
__global__ void coords_k() {
    int idx = blockIdx.x*256 + threadIdx.x;
    if (idx >= MROWS*KTAPS) return;
    int tap = idx % KTAPS;
    int gp  = idx / KTAPS;
    int p   = gp % HW;
    int y   = p / WW, x = p % WW;
    const float* om = g_om + (size_t)gp*NOFF;
    float dy = om[2*tap], dx = om[2*tap + 1];
    float m  = 1.0f / (1.0f + expf(-om[18 + tap]));
    float ys = (float)(y + tap/3 - 1) + dy;
    float xs = (float)(x + tap%3 - 1) + dx;
    float fy0 = floorf(ys), fx0 = floorf(xs);
    int y0 = (int)fy0, x0 = (int)fx0;
    int y1 = y0 + 1,   x1 = x0 + 1;
    float wy1 = ys - fy0, wx1 = xs - fx0;
    float wy0 = 1.0f - wy1, wx0 = 1.0f - wx1;
    int y0c = min(max(y0,0),HH-1), y1c = min(max(y1,0),HH-1);
    int x0c = min(max(x0,0),WW-1), x1c = min(max(x1,0),WW-1);
    float vy0 = ((unsigned)y0 < HH) ? 1.0f : 0.0f;
    float vy1 = ((unsigned)y1 < HH) ? 1.0f : 0.0f;
    float vx0 = ((unsigned)x0 < WW) ? 1.0f : 0.0f;
    float vx1 = ((unsigned)x1 < WW) ? 1.0f : 0.0f;
    SInfo s;
    s.i0 = y0c*WW + x0c;  s.w0 = wy0*wx0*m*vy0*vx0;
    s.i1 = y0c*WW + x1c;  s.w1 = wy0*wx1*m*vy0*vx1;
    s.i2 = y1c*WW + x0c;  s.w2 = wy1*wx0*m*vy1*vx0;
    s.i3 = y1c*WW + x1c;  s.w3 = wy1*wx1*m*vy1*vx1;
    g_sinfo[idx] = s;
}

// ---------------- deformable conv: gather-fused implicit GEMM ----------------
// M=18432, N=256, K=2304.  BM=64, BN=256, BK=32; 256 thr; 8x8 micro; ReLU; NHWC out.
__launch_bounds__(256, 2)
__global__ void gemm_main_k(int layer) {
    __shared__ float As[32][64];
    __shared__ float Bs[32][256];
    const float* in  = (layer == 0) ? g_xT  : g_h1T;
    const float* Bw  = g_bwmain[layer];
    float*       out = (layer == 0) ? g_h1T : g_h2T;
    int tid = threadIdx.x;
    int bm  = blockIdx.x;
    int ty  = tid >> 5, tx = tid & 31;       // compute mapping (8 rows x 8 cols)
    int px  = tid & 63, cg = tid >> 6;       // staging mapping
    int cc  = cg * 8;
    int gp  = bm*64 + px;
    int b   = gp / HW;
    const float* inb = in + (size_t)b*HW*CH;
    const SInfo* sinfo = g_sinfo + (size_t)gp*KTAPS;

    float acc[8][8] = {};

    #pragma unroll 1
    for (int tap = 0; tap < KTAPS; tap++) {
        SInfo s = sinfo[tap];
        const float* q0 = inb + (size_t)s.i0*CH + cc;
        const float* q1 = inb + (size_t)s.i1*CH + cc;
        const float* q2 = inb + (size_t)s.i2*CH + cc;
        const float* q3 = inb + (size_t)s.i3*CH + cc;
        #pragma unroll 1
        for (int cb = 0; cb < 8; cb++) {
            int c0 = cb * 32;
            // --- gmem loads (before sync) ---
            float4 a00 = *(const float4*)(q0 + c0);
            float4 a10 = *(const float4*)(q1 + c0);
            float4 a20 = *(const float4*)(q2 + c0);
            float4 a30 = *(const float4*)(q3 + c0);
            float4 a01 = *(const float4*)(q0 + c0 + 4);
            float4 a11 = *(const float4*)(q1 + c0 + 4);
            float4 a21 = *(const float4*)(q2 + c0 + 4);
            float4 a31 = *(const float4*)(q3 + c0 + 4);
            float r[8];
            r[0] = s.w0*a00.x + s.w1*a10.x + s.w2*a20.x + s.w3*a30.x;
            r[1] = s.w0*a00.y + s.w1*a10.y + s.w2*a20.y + s.w3*a30.y;
            r[2] = s.w0*a00.z + s.w1*a10.z + s.w2*a20.z + s.w3*a30.z;
            r[3] = s.w0*a00.w + s.w1*a10.w + s.w2*a20.w + s.w3*a30.w;
            r[4] = s.w0*a01.x + s.w1*a11.x + s.w2*a21.x + s.w3*a31.x;
            r[5] = s.w0*a01.y + s.w1*a11.y + s.w2*a21.y + s.w3*a31.y;
            r[6] = s.w0*a01.z + s.w1*a11.z + s.w2*a21.z + s.w3*a31.z;
            r[7] = s.w0*a01.w + s.w1*a11.w + s.w2*a21.w + s.w3*a31.w;
            float4 bfrag[8];
            const float4* bsrc = (const float4*)(Bw + (size_t)(tap*CH + c0)*OUTC);
            #pragma unroll
            for (int i = 0; i < 8; i++) bfrag[i] = bsrc[tid + i*256];

            __syncthreads();
            #pragma unroll
            for (int j = 0; j < 8; j++) As[cc+j][px] = r[j];
            #pragma unroll
            for (int i = 0; i < 8; i++) ((float4*)Bs)[tid + i*256] = bfrag[i];
            __syncthreads();

            #pragma unroll
            for (int kk = 0; kk < 32; kk++) {
                float a[8], bb[8];
                *(float4*)&a[0]  = *(const float4*)&As[kk][ty*8];
                *(float4*)&a[4]  = *(const float4*)&As[kk][ty*8 + 4];
                *(float4*)&bb[0] = *(const float4*)&Bs[kk][tx*8];
                *(float4*)&bb[4] = *(const float4*)&Bs[kk][tx*8 + 4];
                #pragma unroll
                for (int i = 0; i < 8; i++)
                    #pragma unroll
                    for (int j = 0; j < 8; j++)
                        acc[i][j] += a[i]*bb[j];
            }
        }
    }

    #pragma unroll
    for (int i = 0; i < 8; i++) {
        int row = bm*64 + ty*8 + i;
        float* orow = out + (size_t)row*OUTC + tx*8;
        float4 o0, o1;
        o0.x = fmaxf(acc[i][0], 0.f); o0.y = fmaxf(acc[i][1], 0.f);
        o0.z = fmaxf(acc[i][2], 0.f); o0.w = fmaxf(acc[i][3], 0.f);
        o1.x = fmaxf(acc[i][4], 0.f); o1.y = fmaxf(acc[i][5], 0.f);
        o1.z = fmaxf(acc[i][6], 0.f); o1.w = fmaxf(acc[i][7], 0.f);
        *(float4*)orow       = o0;
        *(float4*)(orow + 4) = o1;
    }
}

// ---------------- launch ----------------
extern "C" void kernel_launch(void* const* d_in, const int* in_sizes, int n_in,
                              void* d_out, int out_size) {
    (void)in_sizes; (void)n_in; (void)out_size;
    const float* x      = (const float*)d_in[0];
    const float* w_off0 = (const float*)d_in[1];
    const float* b_off0 = (const float*)d_in[2];
    const float* w0     = (const float*)d_in[3];
    const float* w_off1 = (const float*)d_in[4];
    const float* b_off1 = (const float*)d_in[5];
    const float* w1     = (const float*)d_in[6];
    float* out = (float*)d_out;

    prep_woff_k <<<(KDIM*NOFF + 255)/256, 256>>>(w_off0, 0);
    prep_woff_k <<<(KDIM*NOFF + 255)/256, 256>>>(w_off1, 1);
    prep_wmain_k<<<(KDIM*OUTC + 255)/256, 256>>>(w0, 0);
    prep_wmain_k<<<(KDIM*OUTC + 255)/256, 256>>>(w1, 1);

    dim3 tb(32, 8);
    dim3 tg(HW/32, CH/32, BATCH);
    nchw_to_nhwc_k<<<tg, tb>>>(x);

    // layer 1
    gemm_off_k <<<MROWS/128, 256>>>(0, b_off0);
    coords_k   <<<(MROWS*KTAPS + 255)/256, 256>>>();
    gemm_main_k<<<MROWS/64, 256>>>(0);

    // layer 2
    gemm_off_k <<<MROWS/128, 256>>>(1, b_off1);
    coords_k   <<<(MROWS*KTAPS + 255)/256, 256>>>();
    gemm_main_k<<<MROWS/64, 256>>>(1);

    nhwc_to_nchw_k<<<tg, tb>>>(out);
}

// round 4
// speedup vs baseline: 1.0024x; 1.0024x over previous
#include <cuda_runtime.h>
#include <math.h>

#define BATCH 2
#define CH    256
#define HH    96
#define WW    96
#define HW    (HH*WW)        // 9216
#define OUTC  256
#define KTAPS 9
#define KDIM  (KTAPS*CH)     // 2304
#define MROWS (BATCH*HW)     // 18432
#define NOFF  32             // 27 padded to 32

struct __align__(16) SInfo { int i0,i1,i2,i3; float w0,w1,w2,w3; };

// ---- scratch (device globals: allocation-free) ----
__device__ float g_xT [MROWS*CH];        // x in NHWC     [b*HW+p][c]
__device__ float g_h1T[MROWS*CH];        // layer-1 out NHWC
__device__ float g_h2T[MROWS*CH];        // layer-2 out NHWC
__device__ float g_om [MROWS*NOFF];      // offset-conv out per pixel (27 used)
__device__ SInfo g_sinfo[MROWS*KTAPS];   // per (pixel,tap) bilinear indices+weights
__device__ float g_bwoff [2][KDIM*NOFF]; // offset weights, K-major [k][j]
__device__ float g_bwmain[2][KDIM*OUTC]; // main weights,   K-major [k][o]

// ---------------- weight prep (transpose to K-major) ----------------
__global__ void prep_woff_k(const float* __restrict__ woff, int layer) {
    int idx = blockIdx.x*256 + threadIdx.x;
    if (idx >= KDIM*NOFF) return;
    int j   = idx & 31;
    int kc  = idx >> 5;
    int tap = kc / CH, c = kc % CH;
    g_bwoff[layer][idx] = (j < 27) ? woff[(j*CH + c)*KTAPS + tap] : 0.0f;
}

__global__ void prep_wmain_k(const float* __restrict__ w, int layer) {
    int idx = blockIdx.x*256 + threadIdx.x;
    if (idx >= KDIM*OUTC) return;
    int o   = idx & 255;
    int kc  = idx >> 8;
    int tap = kc / CH, c = kc % CH;
    g_bwmain[layer][idx] = w[(o*CH + c)*KTAPS + tap];
}

// ---------------- layout transposes ----------------
__global__ void nchw_to_nhwc_k(const float* __restrict__ src) {
    __shared__ float t[32][33];
    int b  = blockIdx.z;
    int p0 = blockIdx.x*32, c0 = blockIdx.y*32;
    int tx = threadIdx.x,  ty = threadIdx.y;
    #pragma unroll
    for (int i = 0; i < 32; i += 8)
        t[ty+i][tx] = src[(size_t)(b*CH + c0+ty+i)*HW + p0 + tx];
    __syncthreads();
    #pragma unroll
    for (int i = 0; i < 32; i += 8)
        g_xT[(size_t)(b*HW + p0+ty+i)*CH + c0 + tx] = t[tx][ty+i];
}

__global__ void nhwc_to_nchw_k(float* __restrict__ dst) {
    __shared__ float t[32][33];
    int b  = blockIdx.z;
    int p0 = blockIdx.x*32, c0 = blockIdx.y*32;
    int tx = threadIdx.x,  ty = threadIdx.y;
    #pragma unroll
    for (int i = 0; i < 32; i += 8)
        t[ty+i][tx] = g_h2T[(size_t)(b*HW + p0+ty+i)*CH + c0 + tx];
    __syncthreads();
    #pragma unroll
    for (int i = 0; i < 32; i += 8)
        dst[(size_t)(b*CH + c0+ty+i)*HW + p0 + tx] = t[tx][ty+i];
}

// ---------------- offset conv: implicit-im2col GEMM ----------------
// M=18432, N=32 (27 used), K=2304.  BM=128, BN=32, BK=32; 256 thr; 4x4 micro.
__launch_bounds__(256, 2)
__global__ void gemm_off_k(int layer, const float* __restrict__ bias) {
    __shared__ float As[32][128];
    __shared__ float Bs[32][32];
    const float* in = (layer == 0) ? g_xT : g_h1T;
    const float* Bw = g_bwoff[layer];
    int tid = threadIdx.x;
    int bm  = blockIdx.x;
    int ty  = tid >> 3, tx = tid & 7;        // compute mapping
    int px  = tid & 127, cg = tid >> 7;      // staging mapping
    int cc  = cg * 16;
    int gp  = bm*128 + px;
    int b   = gp / HW, p = gp % HW;
    int y   = p / WW, x = p % WW;
    const float* inb = in + (size_t)b*HW*CH;

    float acc[4][4] = {};

    for (int kt = 0; kt < 72; kt++) {
        int tap = kt >> 3;
        int c0  = (kt & 7) * 32;
        // --- gmem loads (before sync) ---
        float4 bfrag = ((const float4*)(Bw + (size_t)(tap*CH + c0)*NOFF))[tid];
        int ny = y + tap/3 - 1;
        int nx = x + tap%3 - 1;
        float4 d0 = {0,0,0,0}, d1 = d0, d2 = d0, d3 = d0;
        if ((unsigned)ny < HH && (unsigned)nx < WW) {
            const float* s = inb + (size_t)(ny*WW + nx)*CH + c0 + cc;
            d0 = *(const float4*)(s);
            d1 = *(const float4*)(s + 4);
            d2 = *(const float4*)(s + 8);
            d3 = *(const float4*)(s + 12);
        }
        __syncthreads();
        As[cc+ 0][px]=d0.x; As[cc+ 1][px]=d0.y; As[cc+ 2][px]=d0.z; As[cc+ 3][px]=d0.w;
        As[cc+ 4][px]=d1.x; As[cc+ 5][px]=d1.y; As[cc+ 6][px]=d1.z; As[cc+ 7][px]=d1.w;
        As[cc+ 8][px]=d2.x; As[cc+ 9][px]=d2.y; As[cc+10][px]=d2.z; As[cc+11][px]=d2.w;
        As[cc+12][px]=d3.x; As[cc+13][px]=d3.y; As[cc+14][px]=d3.z; As[cc+15][px]=d3.w;
        ((float4*)Bs)[tid] = bfrag;
        __syncthreads();

        #pragma unroll
        for (int kk = 0; kk < 32; kk++) {
            float a[4], bb[4];
            *(float4*)a  = *(const float4*)&As[kk][ty*4];
            *(float4*)bb = *(const float4*)&Bs[kk][tx*4];
            #pragma unroll
            for (int i = 0; i < 4; i++)
                #pragma unroll
                for (int j = 0; j < 4; j++)
                    acc[i][j] += a[i]*bb[j];
        }
    }

    int j0 = tx*4;
    float bv[4];
    #pragma unroll
    for (int j = 0; j < 4; j++) bv[j] = (j0 + j < 27) ? bias[j0 + j] : 0.0f;
    #pragma unroll
    for (int i = 0; i < 4; i++) {
        int row = bm*128 + ty*4 + i;
        float4 o4 = make_float4(acc[i][0]+bv[0], acc[i][1]+bv[1],
                                acc[i][2]+bv[2], acc[i][3]+bv[3]);
        *(float4*)&g_om[(size_t)row*NOFF + j0] = o4;
    }
}

// ---------------- sample coordinates + bilinear weights ----------------
__global__ void coords_k() {
    int idx = blockIdx.x*256 + threadIdx.x;
    if (idx >= MROWS*KTAPS) return;
    int tap = idx % KTAPS;
    int gp  = idx / KTAPS;
    int p   = gp % HW;
    int y   = p / WW, x = p % WW;
    const float* om = g_om + (size_t)gp*NOFF;
    float dy = om[2*tap], dx = om[2*tap + 1];
    float m  = 1.0f / (1.0f + expf(-om[18 + tap]));
    float ys = (float)(y + tap/3 - 1) + dy;
    float xs = (float)(x + tap%3 - 1) + dx;
    float fy0 = floorf(ys), fx0 = floorf(xs);
    int y0 = (int)fy0, x0 = (int)fx0;
    int y1 = y0 + 1,   x1 = x0 + 1;
    float wy1 = ys - fy0, wx1 = xs - fx0;
    float wy0 = 1.0f - wy1, wx0 = 1.0f - wx1;
    int y0c = min(max(y0,0),HH-1), y1c = min(max(y1,0),HH-1);
    int x0c = min(max(x0,0),WW-1), x1c = min(max(x1,0),WW-1);
    float vy0 = ((unsigned)y0 < HH) ? 1.0f : 0.0f;
    float vy1 = ((unsigned)y1 < HH) ? 1.0f : 0.0f;
    float vx0 = ((unsigned)x0 < WW) ? 1.0f : 0.0f;
    float vx1 = ((unsigned)x1 < WW) ? 1.0f : 0.0f;
    SInfo s;
    s.i0 = y0c*WW + x0c;  s.w0 = wy0*wx0*m*vy0*vx0;
    s.i1 = y0c*WW + x1c;  s.w1 = wy0*wx1*m*vy0*vx1;
    s.i2 = y1c*WW + x0c;  s.w2 = wy1*wx0*m*vy1*vx0;
    s.i3 = y1c*WW + x1c;  s.w3 = wy1*wx1*m*vy1*vx1;
    g_sinfo[idx] = s;
}

// ---------------- deformable conv: gather-fused implicit GEMM ----------------
// M=18432, N=256, K=2304.  BM=64, BN=256, BK=32; 256 thr; 8x8 micro; ReLU; NHWC out.
__launch_bounds__(256, 2)
__global__ void gemm_main_k(int layer) {
    __shared__ float As[32][64];
    __shared__ float Bs[32][256];
    const float* in  = (layer == 0) ? g_xT  : g_h1T;
    const float* Bw  = g_bwmain[layer];
    float*       out = (layer == 0) ? g_h1T : g_h2T;
    int tid = threadIdx.x;
    int bm  = blockIdx.x;
    int ty  = tid >> 5, tx = tid & 31;       // compute mapping (8 rows x 8 cols)
    int px  = tid & 63, cg = tid >> 6;       // staging mapping
    int cc  = cg * 8;
    int gp  = bm*64 + px;
    int b   = gp / HW;
    const float* inb = in + (size_t)b*HW*CH;
    const SInfo* sinfo = g_sinfo + (size_t)gp*KTAPS;

    float acc[8][8] = {};

    #pragma unroll 1
    for (int tap = 0; tap < KTAPS; tap++) {
        SInfo s = sinfo[tap];
        const float* q0 = inb + (size_t)s.i0*CH + cc;
        const float* q1 = inb + (size_t)s.i1*CH + cc;
        const float* q2 = inb + (size_t)s.i2*CH + cc;
        const float* q3 = inb + (size_t)s.i3*CH + cc;
        #pragma unroll 1
        for (int cb = 0; cb < 8; cb++) {
            int c0 = cb * 32;
            // --- gmem loads (before sync) ---
            float4 a00 = *(const float4*)(q0 + c0);
            float4 a10 = *(const float4*)(q1 + c0);
            float4 a20 = *(const float4*)(q2 + c0);
            float4 a30 = *(const float4*)(q3 + c0);
            float4 a01 = *(const float4*)(q0 + c0 + 4);
            float4 a11 = *(const float4*)(q1 + c0 + 4);
            float4 a21 = *(const float4*)(q2 + c0 + 4);
            float4 a31 = *(const float4*)(q3 + c0 + 4);
            float r[8];
            r[0] = s.w0*a00.x + s.w1*a10.x + s.w2*a20.x + s.w3*a30.x;
            r[1] = s.w0*a00.y + s.w1*a10.y + s.w2*a20.y + s.w3*a30.y;
            r[2] = s.w0*a00.z + s.w1*a10.z + s.w2*a20.z + s.w3*a30.z;
            r[3] = s.w0*a00.w + s.w1*a10.w + s.w2*a20.w + s.w3*a30.w;
            r[4] = s.w0*a01.x + s.w1*a11.x + s.w2*a21.x + s.w3*a31.x;
            r[5] = s.w0*a01.y + s.w1*a11.y + s.w2*a21.y + s.w3*a31.y;
            r[6] = s.w0*a01.z + s.w1*a11.z + s.w2*a21.z + s.w3*a31.z;
            r[7] = s.w0*a01.w + s.w1*a11.w + s.w2*a21.w + s.w3*a31.w;
            float4 bfrag[8];
            const float4* bsrc = (const float4*)(Bw + (size_t)(tap*CH + c0)*OUTC);
            #pragma unroll
            for (int i = 0; i < 8; i++) bfrag[i] = bsrc[tid + i*256];

            __syncthreads();
            #pragma unroll
            for (int j = 0; j < 8; j++) As[cc+j][px] = r[j];
            #pragma unroll
            for (int i = 0; i < 8; i++) ((float4*)Bs)[tid + i*256] = bfrag[i];
            __syncthreads();

            #pragma unroll
            for (int kk = 0; kk < 32; kk++) {
                float a[8], bb[8];
                *(float4*)&a[0]  = *(const float4*)&As[kk][ty*8];
                *(float4*)&a[4]  = *(const float4*)&As[kk][ty*8 + 4];
                *(float4*)&bb[0] = *(const float4*)&Bs[kk][tx*8];
                *(float4*)&bb[4] = *(const float4*)&Bs[kk][tx*8 + 4];
                #pragma unroll
                for (int i = 0; i < 8; i++)
                    #pragma unroll
                    for (int j = 0; j < 8; j++)
                        acc[i][j] += a[i]*bb[j];
            }
        }
    }

    #pragma unroll
    for (int i = 0; i < 8; i++) {
        int row = bm*64 + ty*8 + i;
        float* orow = out + (size_t)row*OUTC + tx*8;
        float4 o0, o1;
        o0.x = fmaxf(acc[i][0], 0.f); o0.y = fmaxf(acc[i][1], 0.f);
        o0.z = fmaxf(acc[i][2], 0.f); o0.w = fmaxf(acc[i][3], 0.f);
        o1.x = fmaxf(acc[i][4], 0.f); o1.y = fmaxf(acc[i][5], 0.f);
        o1.z = fmaxf(acc[i][6], 0.f); o1.w = fmaxf(acc[i][7], 0.f);
        *(float4*)orow       = o0;
        *(float4*)(orow + 4) = o1;
    }
}

// ---------------- launch ----------------
extern "C" void kernel_launch(void* const* d_in, const int* in_sizes, int n_in,
                              void* d_out, int out_size) {
    (void)in_sizes; (void)n_in; (void)out_size;
    const float* x      = (const float*)d_in[0];
    const float* w_off0 = (const float*)d_in[1];
    const float* b_off0 = (const float*)d_in[2];
    const float* w0     = (const float*)d_in[3];
    const float* w_off1 = (const float*)d_in[4];
    const float* b_off1 = (const float*)d_in[5];
    const float* w1     = (const float*)d_in[6];
    float* out = (float*)d_out;

    prep_woff_k <<<(KDIM*NOFF + 255)/256, 256>>>(w_off0, 0);
    prep_woff_k <<<(KDIM*NOFF + 255)/256, 256>>>(w_off1, 1);
    prep_wmain_k<<<(KDIM*OUTC + 255)/256, 256>>>(w0, 0);
    prep_wmain_k<<<(KDIM*OUTC + 255)/256, 256>>>(w1, 1);

    dim3 tb(32, 8);
    dim3 tg(HW/32, CH/32, BATCH);
    nchw_to_nhwc_k<<<tg, tb>>>(x);

    // layer 1
    gemm_off_k <<<MROWS/128, 256>>>(0, b_off0);
    coords_k   <<<(MROWS*KTAPS + 255)/256, 256>>>();
    gemm_main_k<<<MROWS/64, 256>>>(0);

    // layer 2
    gemm_off_k <<<MROWS/128, 256>>>(1, b_off1);
    coords_k   <<<(MROWS*KTAPS + 255)/256, 256>>>();
    gemm_main_k<<<MROWS/64, 256>>>(1);

    nhwc_to_nchw_k<<<tg, tb>>>(out);
}